// round 2
// baseline (speedup 1.0000x reference)
#include <cuda_runtime.h>

#define BB 32
#define C 64
#define H 128
#define W 128
#define OUTC 64
#define KS 3
#define HIDDEN 128
#define WPB (OUTC*C*KS*KS)   // 36864 weights per sample

// scratch (no allocations allowed)
__device__ float g_stats[BB*C];
__device__ float g_hidden[BB*HIDDEN];
__device__ float g_weight[(size_t)BB*WPB];

// ---------------- Kernel 1: per-(b,c) spatial mean ----------------
__global__ void stats_kernel(const float* __restrict__ x, float* __restrict__ stats) {
    int bc = blockIdx.x;                       // 0..B*C-1
    const float4* p = (const float4*)(x + (size_t)bc * (H*W));
    float s = 0.f;
    for (int i = threadIdx.x; i < (H*W)/4; i += 256) {
        float4 v = p[i];
        s += (v.x + v.y) + (v.z + v.w);
    }
    #pragma unroll
    for (int o = 16; o; o >>= 1) s += __shfl_down_sync(0xffffffffu, s, o);
    __shared__ float sm[8];
    if ((threadIdx.x & 31) == 0) sm[threadIdx.x >> 5] = s;
    __syncthreads();
    if (threadIdx.x < 8) {
        s = sm[threadIdx.x];
        #pragma unroll
        for (int o = 4; o; o >>= 1) s += __shfl_down_sync(0xffu, s, o);
        if (threadIdx.x == 0) stats[bc] = s * (1.0f / (H*W));
    }
}

// ---------------- Kernel 2: hidden = relu(stats @ W1 + b1) ----------------
__global__ void hidden_kernel(const float* __restrict__ stats,
                              const float* __restrict__ W1,
                              const float* __restrict__ b1,
                              float* __restrict__ hidden) {
    int b = blockIdx.x;
    int j = threadIdx.x;                       // 0..127
    __shared__ float s[C];
    if (j < C) s[j] = stats[b*C + j];
    __syncthreads();
    float acc = b1[j];
    #pragma unroll
    for (int c = 0; c < C; c++) acc = fmaf(s[c], W1[c*HIDDEN + j], acc);
    hidden[b*HIDDEN + j] = fmaxf(acc, 0.f);
}

// ---------------- Kernel 3: weight = hidden @ W2 + b2 ----------------
// One thread per output column j; accumulates all 32 batches so each W2
// column is read exactly once from gmem.
__global__ void weight_kernel(const float* __restrict__ hidden,
                              const float* __restrict__ W2,
                              const float* __restrict__ b2,
                              float* __restrict__ weight) {
    __shared__ float sh[BB*HIDDEN];            // 4096 floats = 16 KB
    for (int i = threadIdx.x; i < BB*HIDDEN; i += blockDim.x) sh[i] = hidden[i];
    __syncthreads();
    int j = blockIdx.x * blockDim.x + threadIdx.x;   // < 36864
    float bias = b2[j];
    float acc[BB];
    #pragma unroll
    for (int b = 0; b < BB; b++) acc[b] = bias;
    for (int k = 0; k < HIDDEN; k++) {
        float w = W2[(size_t)k * WPB + j];
        #pragma unroll
        for (int b = 0; b < BB; b++) acc[b] = fmaf(sh[b*HIDDEN + k], w, acc[b]);
    }
    #pragma unroll
    for (int b = 0; b < BB; b++) weight[(size_t)b * WPB + j] = acc[b];
}

// ---------------- Kernel 4: per-sample 3x3 conv (the 38.6 GFLOP) ----------------
// Block: 1 batch x 16 out-channels x 16x16 spatial tile, 256 threads.
// Thread: 1 o-channel x 4x4 pixel subtile -> 9 weights in regs, 6x6 input
// patch in regs, 144 FMA per input channel.
#define TO 16
#define TS 16
#define CCH 8
#define XP 19    // x smem pitch (avoids conflicts)
#define WPITCH 73 // weight smem o-stride (odd -> conflict-free)

__global__ __launch_bounds__(256, 2)
void conv_kernel(const float* __restrict__ x,
                 const float* __restrict__ weight,
                 float* __restrict__ out) {
    __shared__ float s_x[CCH*18*XP];   // 2736 floats
    __shared__ float s_w[TO*WPITCH];   // 1168 floats

    int tile = blockIdx.x;             // 0..63  (8x8 tiles of 16x16)
    int ty0 = (tile >> 3) * TS;
    int tx0 = (tile & 7) * TS;
    int og0 = blockIdx.y * TO;
    int b   = blockIdx.z;
    int tid = threadIdx.x;
    int o   = tid & 15;
    int pg  = tid >> 4;
    int sy  = (pg >> 2) << 2;
    int sx  = (pg & 3) << 2;

    const float* xb = x + (size_t)b * C * H * W;
    const float* wb = g_weight + (size_t)b * WPB;
    (void)weight;

    float acc[4][4];
    #pragma unroll
    for (int i = 0; i < 4; i++)
        #pragma unroll
        for (int j = 0; j < 4; j++) acc[i][j] = 0.f;

    for (int cc = 0; cc < C; cc += CCH) {
        __syncthreads();
        // stage x tile [CCH][18][18] (with halo, zero-padded at borders)
        for (int idx = tid; idx < CCH*18*18; idx += 256) {
            int c  = idx / (18*18);
            int r  = idx - c*(18*18);
            int yy = r / 18;
            int xx = r - yy*18;
            int gy = ty0 + yy - 1, gx = tx0 + xx - 1;
            float v = 0.f;
            if ((unsigned)gy < (unsigned)H && (unsigned)gx < (unsigned)W)
                v = xb[(size_t)(cc + c) * (H*W) + gy*W + gx];
            s_x[c*18*XP + yy*XP + xx] = v;
        }
        // stage weights [TO][CCH][9]
        for (int idx = tid; idx < TO*CCH*9; idx += 256) {
            int oo = idx / (CCH*9);
            int r  = idx - oo*(CCH*9);         // c*9 + k
            int c  = r / 9;
            int k  = r - c*9;
            s_w[oo*WPITCH + r] = wb[(size_t)((og0 + oo)*C + cc + c)*9 + k];
        }
        __syncthreads();

        #pragma unroll
        for (int c = 0; c < CCH; c++) {
            const float* sxc = &s_x[c*18*XP];
            float xv[6][6];
            #pragma unroll
            for (int i = 0; i < 6; i++)
                #pragma unroll
                for (int j = 0; j < 6; j++)
                    xv[i][j] = sxc[(sy + i)*XP + sx + j];
            float wr[9];
            #pragma unroll
            for (int k = 0; k < 9; k++) wr[k] = s_w[o*WPITCH + c*9 + k];
            #pragma unroll
            for (int py = 0; py < 4; py++)
                #pragma unroll
                for (int px = 0; px < 4; px++) {
                    float a = acc[py][px];
                    #pragma unroll
                    for (int kh = 0; kh < 3; kh++)
                        #pragma unroll
                        for (int kw = 0; kw < 3; kw++)
                            a = fmaf(xv[py+kh][px+kw], wr[kh*3+kw], a);
                    acc[py][px] = a;
                }
        }
    }

    float* ob = out + ((size_t)(b*OUTC + og0 + o) * H + ty0 + sy) * W + tx0 + sx;
    #pragma unroll
    for (int py = 0; py < 4; py++) {
        float4 v = make_float4(acc[py][0], acc[py][1], acc[py][2], acc[py][3]);
        *(float4*)(ob + (size_t)py*W) = v;
    }
}

extern "C" void kernel_launch(void* const* d_in, const int* in_sizes, int n_in,
                              void* d_out, int out_size) {
    const float* x  = (const float*)d_in[0];   // [32,64,128,128]
    const float* W1 = (const float*)d_in[1];   // [64,128]
    const float* b1 = (const float*)d_in[2];   // [128]
    const float* W2 = (const float*)d_in[3];   // [128,36864]
    const float* b2 = (const float*)d_in[4];   // [36864]
    float* out = (float*)d_out;                // [32,64,128,128]

    float* stats;  cudaGetSymbolAddress((void**)&stats,  g_stats);
    float* hidden; cudaGetSymbolAddress((void**)&hidden, g_hidden);
    float* weight; cudaGetSymbolAddress((void**)&weight, g_weight);

    stats_kernel<<<BB*C, 256>>>(x, stats);
    hidden_kernel<<<BB, HIDDEN>>>(stats, W1, b1, hidden);
    weight_kernel<<<WPB/128, 128>>>(hidden, W2, b2, weight);
    dim3 grid(64, OUTC/TO, BB);
    conv_kernel<<<grid, 256>>>(x, weight, out);
}